// round 13
// baseline (speedup 1.0000x reference)
#include <cuda_runtime.h>
#include <cuda_bf16.h>
#include <cuda_fp16.h>
#include <math.h>
#include <stdint.h>

// TopKRouter: x[4,4096,4096] fp32, gate_w[64,4096] fp32
// logits = x @ w^T [16384,64]; softmax; top-2; z_loss = mean(logits^2)
// out fp32: [0,32768) idx | [32768,65536) scores | [65536] aux=0 | [65537] z_loss
//
// sm_103 BASE target. mma.sync fp16 hi/lo split:
//   pass1: Ah*Bh  fp16 inputs, FP32 accumulate (partials ~1)
//   pass2: Ah*Bl + Al*Bh  fp16 inputs, FP16 accumulate (partials ~1e-4; 2x rate)
// A: direct LDG fragment loads (no smem). B: smem staged, double-buffered.
// MT=64/CTA, 256 thr, grid=256, 2 CTAs/SM. Inline exact-fp32 fixup for
// ambiguous top-k gaps; finalize merged via last-block atomic.

#define M_TOT 16384
#define H_DIM 4096
#define E_NUM 64
#define MT    64
#define KC    64
#define NC    (H_DIM / KC)     // 64
#define NBLK  (M_TOT / MT)     // 256
#define NTHR  256
#define GAP_TH 2.5e-3f

// B stage: BH 0 | BL 8192 ; stage size 16 KB; two stages
#define BH_O 0
#define BL_O 8192
#define BSTG 16384
#define DSMB (1024 + 2 * BSTG)   // 33792

__device__ float g_partials[NBLK];
__device__ unsigned int g_done = 0;

__device__ __forceinline__ uint32_t smem_u32(const void* p) {
    uint32_t a;
    asm("{ .reg .u64 t; cvta.to.shared.u64 t, %1; cvt.u32.u64 %0, t; }" : "=r"(a) : "l"(p));
    return a;
}

#define LDM4(r, a) \
    asm volatile("ldmatrix.sync.aligned.m8n8.x4.shared.b16 {%0,%1,%2,%3}, [%4];" \
        : "=r"((r)[0]), "=r"((r)[1]), "=r"((r)[2]), "=r"((r)[3]) : "r"(a))

// fp16 inputs, fp32 accumulate
#define MMAF32(c, a, b0, b1) \
    asm volatile("mma.sync.aligned.m16n8k16.row.col.f32.f16.f16.f32 " \
        "{%0,%1,%2,%3},{%4,%5,%6,%7},{%8,%9},{%0,%1,%2,%3};" \
        : "+f"((c)[0]), "+f"((c)[1]), "+f"((c)[2]), "+f"((c)[3]) \
        : "r"((a)[0]), "r"((a)[1]), "r"((a)[2]), "r"((a)[3]), "r"(b0), "r"(b1))

// fp16 inputs, fp16 accumulate (2 regs = 4 halves, same c0..c3 positions)
#define MMAF16(c, a, b0, b1) \
    asm volatile("mma.sync.aligned.m16n8k16.row.col.f16.f16.f16.f16 " \
        "{%0,%1},{%2,%3,%4,%5},{%6,%7},{%0,%1};" \
        : "+r"((c)[0]), "+r"((c)[1]) \
        : "r"((a)[0]), "r"((a)[1]), "r"((a)[2]), "r"((a)[3]), "r"(b0), "r"(b1))

// split float4 into fp16 hi/lo quads, store 8B each (swizzled, 128B rows) — B path
__device__ __forceinline__ void cvtst(float4 v, uint32_t hi, uint32_t lo, int row, int q) {
    uint32_t off = (uint32_t)row * 128u + (((uint32_t)q * 8u) ^ (((uint32_t)row & 7u) << 4));
    __half2 h01 = __float22half2_rn(make_float2(v.x, v.y));
    __half2 h23 = __float22half2_rn(make_float2(v.z, v.w));
    float2 f01 = __half22float2(h01);
    float2 f23 = __half22float2(h23);
    __half2 l01 = __float22half2_rn(make_float2(v.x - f01.x, v.y - f01.y));
    __half2 l23 = __float22half2_rn(make_float2(v.z - f23.x, v.w - f23.y));
    uint32_t uh01 = *reinterpret_cast<uint32_t*>(&h01);
    uint32_t uh23 = *reinterpret_cast<uint32_t*>(&h23);
    uint32_t ul01 = *reinterpret_cast<uint32_t*>(&l01);
    uint32_t ul23 = *reinterpret_cast<uint32_t*>(&l23);
    asm volatile("st.shared.v2.u32 [%0], {%1,%2};" :: "r"(hi + off), "r"(uh01), "r"(uh23) : "memory");
    asm volatile("st.shared.v2.u32 [%0], {%1,%2};" :: "r"(lo + off), "r"(ul01), "r"(ul23) : "memory");
}

// convert one float2 (k-adjacent pair) to fp16x2 hi + lo (elem0 in low half)
__device__ __forceinline__ void cvt2(float2 v, uint32_t& h, uint32_t& l) {
    __half2 hh = __float22half2_rn(v);
    float2 f = __half22float2(hh);
    __half2 ll = __float22half2_rn(make_float2(v.x - f.x, v.y - f.y));
    h = *reinterpret_cast<uint32_t*>(&hh);
    l = *reinterpret_cast<uint32_t*>(&ll);
}

extern __shared__ char dsm_raw[];

__global__ __launch_bounds__(NTHR, 2)
void router_main(const float* __restrict__ x, const float* __restrict__ w,
                 float* __restrict__ out)
{
    __shared__ float zsh[2];
    __shared__ float lg[E_NUM];
    __shared__ int flist[16];
    __shared__ int fcnt;
    __shared__ int is_last;

    const int tid  = threadIdx.x;
    const int lid  = tid & 31;
    const int wid  = tid >> 5;               // 0..7
    const int wm   = wid & 1;                // row half (32 tokens)
    const int wn   = (wid >> 1) & 1;         // expert half (32 experts)
    const int kgrp = wid >> 2;               // k half of each chunk (k32)
    const int m0   = blockIdx.x * MT;
    const int kw   = kgrp * 32;

    uint32_t raw = smem_u32(dsm_raw);
    uint32_t SB  = (raw + 127u) & ~127u;

    // B ldmatrix constants
    const uint32_t sxor  = ((uint32_t)(lid & 7)) << 4;
    const uint32_t boff0 = (uint32_t)(wn * 32 + ((lid >> 4) << 3) + (lid & 7)) * 128u;
    const uint32_t boff1 = boff0 + 2048u;    // +16 experts
    const uint32_t bkx   = ((uint32_t)((lid >> 3) & 1)) << 4;

    // A fragment base: row = m0 + wm*32 + (lid>>2), col base = 2*(lid&3)
    const float* aptr = x + (size_t)(m0 + wm * 32 + (lid >> 2)) * H_DIM + 2 * (lid & 3);

    // B staging lanes
    const int brow = tid >> 4, bq = tid & 15;

    float acc[2][4][4];
    uint32_t acc16[2][4][2];
#pragma unroll
    for (int mi = 0; mi < 2; mi++)
#pragma unroll
        for (int ni = 0; ni < 4; ni++) {
#pragma unroll
            for (int r = 0; r < 4; r++) acc[mi][ni][r] = 0.f;
            acc16[mi][ni][0] = 0u; acc16[mi][ni][1] = 0u;
        }

    if (tid == 0) fcnt = 0;

    float2 S0[8], S1[8];
    float4 rb[4];

    // ---------- prologue ----------
#pragma unroll
    for (int slot = 0; slot < 4; slot++)
        rb[slot] = *(const float4*)&w[(size_t)(brow + slot * 16) * H_DIM + bq * 4];
    {
        uint32_t st0 = SB;
#pragma unroll
        for (int slot = 0; slot < 4; slot++)
            cvtst(rb[slot], st0 + BH_O, st0 + BL_O, brow + slot * 16, bq);
    }
#pragma unroll
    for (int mi = 0; mi < 2; mi++) {
        S0[mi * 4 + 0] = *(const float2*)(aptr + (mi * 16 + 0) * H_DIM + kw + 0);
        S0[mi * 4 + 1] = *(const float2*)(aptr + (mi * 16 + 8) * H_DIM + kw + 0);
        S0[mi * 4 + 2] = *(const float2*)(aptr + (mi * 16 + 0) * H_DIM + kw + 8);
        S0[mi * 4 + 3] = *(const float2*)(aptr + (mi * 16 + 8) * H_DIM + kw + 8);
        S1[mi * 4 + 0] = *(const float2*)(aptr + (mi * 16 + 0) * H_DIM + kw + 16);
        S1[mi * 4 + 1] = *(const float2*)(aptr + (mi * 16 + 8) * H_DIM + kw + 16);
        S1[mi * 4 + 2] = *(const float2*)(aptr + (mi * 16 + 0) * H_DIM + kw + 24);
        S1[mi * 4 + 3] = *(const float2*)(aptr + (mi * 16 + 8) * H_DIM + kw + 24);
    }
#pragma unroll
    for (int slot = 0; slot < 4; slot++)
        rb[slot] = *(const float4*)&w[(size_t)(brow + slot * 16) * H_DIM + KC + bq * 4];
    __syncthreads();

    // ---------- main loop ----------
#pragma unroll 1
    for (int c = 0; c < NC; c++) {
        const uint32_t rbuf = SB + ((c & 1) ? BSTG : 0);
        const uint32_t wbuf = SB + ((c & 1) ? 0 : BSTG);
        const uint32_t BH = rbuf + BH_O, BL = rbuf + BL_O;
        const int kc = c * KC + kw;
        const int kA = (c < NC - 1) ? (kc + KC) : kc;
        const int kB = (c < NC - 2) ? ((c + 2) * KC) : ((NC - 1) * KC);

#pragma unroll
        for (int ks = 0; ks < 2; ks++) {
            float2* S = ks ? S1 : S0;
            uint32_t ah[2][4], al[2][4];
#pragma unroll
            for (int mi = 0; mi < 2; mi++)
#pragma unroll
                for (int j = 0; j < 4; j++)
                    cvt2(S[mi * 4 + j], ah[mi][j], al[mi][j]);
            {
                const int kk = kA + ks * 16;
#pragma unroll
                for (int mi = 0; mi < 2; mi++) {
                    S[mi * 4 + 0] = *(const float2*)(aptr + (mi * 16 + 0) * H_DIM + kk + 0);
                    S[mi * 4 + 1] = *(const float2*)(aptr + (mi * 16 + 8) * H_DIM + kk + 0);
                    S[mi * 4 + 2] = *(const float2*)(aptr + (mi * 16 + 0) * H_DIM + kk + 8);
                    S[mi * 4 + 3] = *(const float2*)(aptr + (mi * 16 + 8) * H_DIM + kk + 8);
                }
            }
            const uint32_t kb  = (uint32_t)(kgrp * 2 + ks) * 32u;
            const uint32_t kbb = (kb + bkx) ^ sxor;
#pragma unroll
            for (int nh = 0; nh < 2; nh++) {
                const uint32_t bo = (nh == 0) ? boff0 : boff1;
                uint32_t bHn[4], bLn[4];
                LDM4(bHn, BH + bo + kbb);
                LDM4(bLn, BL + bo + kbb);
                // hi*hi: fp32 accumulate
#pragma unroll
                for (int mi = 0; mi < 2; mi++)
#pragma unroll
                    for (int nl = 0; nl < 2; nl++)
                        MMAF32(acc[mi][nh * 2 + nl], ah[mi], bHn[nl * 2], bHn[nl * 2 + 1]);
                // cross terms: fp16 accumulate (tiny partials, 2x rate path)
#pragma unroll
                for (int mi = 0; mi < 2; mi++)
#pragma unroll
                    for (int nl = 0; nl < 2; nl++)
                        MMAF16(acc16[mi][nh * 2 + nl], ah[mi], bLn[nl * 2], bLn[nl * 2 + 1]);
#pragma unroll
                for (int mi = 0; mi < 2; mi++)
#pragma unroll
                    for (int nl = 0; nl < 2; nl++)
                        MMAF16(acc16[mi][nh * 2 + nl], al[mi], bHn[nl * 2], bHn[nl * 2 + 1]);
            }
        }

#pragma unroll
        for (int slot = 0; slot < 4; slot++)
            cvtst(rb[slot], wbuf + BH_O, wbuf + BL_O, brow + slot * 16, bq);
#pragma unroll
        for (int slot = 0; slot < 4; slot++)
            rb[slot] = *(const float4*)&w[(size_t)(brow + slot * 16) * H_DIM + kB + bq * 4];
        __syncthreads();
    }

    // fold fp16 cross accumulators into fp32 accs
#pragma unroll
    for (int mi = 0; mi < 2; mi++)
#pragma unroll
        for (int ni = 0; ni < 4; ni++) {
            float2 c01 = __half22float2(*reinterpret_cast<__half2*>(&acc16[mi][ni][0]));
            float2 c23 = __half22float2(*reinterpret_cast<__half2*>(&acc16[mi][ni][1]));
            acc[mi][ni][0] += c01.x; acc[mi][ni][1] += c01.y;
            acc[mi][ni][2] += c23.x; acc[mi][ni][3] += c23.y;
        }

    // ---------- merge kgrp halves + stage logits [64][65] (overlays B stages) ----------
    float* ls = (float*)(dsm_raw + (SB - raw));
    {
        int gr = lid >> 2, tg = lid & 3;
        if (kgrp == 0) {
#pragma unroll
            for (int mi = 0; mi < 2; mi++)
#pragma unroll
                for (int ni = 0; ni < 4; ni++) {
                    int r0 = wm * 32 + mi * 16 + gr;
                    int col = wn * 32 + ni * 8 + tg * 2;
                    ls[r0 * 65 + col]           = acc[mi][ni][0];
                    ls[r0 * 65 + col + 1]       = acc[mi][ni][1];
                    ls[(r0 + 8) * 65 + col]     = acc[mi][ni][2];
                    ls[(r0 + 8) * 65 + col + 1] = acc[mi][ni][3];
                }
        }
        __syncthreads();
        if (kgrp == 1) {
#pragma unroll
            for (int mi = 0; mi < 2; mi++)
#pragma unroll
                for (int ni = 0; ni < 4; ni++) {
                    int r0 = wm * 32 + mi * 16 + gr;
                    int col = wn * 32 + ni * 8 + tg * 2;
                    ls[r0 * 65 + col]           += acc[mi][ni][0];
                    ls[r0 * 65 + col + 1]       += acc[mi][ni][1];
                    ls[(r0 + 8) * 65 + col]     += acc[mi][ni][2];
                    ls[(r0 + 8) * 65 + col + 1] += acc[mi][ni][3];
                }
        }
        __syncthreads();
    }

    // ---------- per-token epilogue: threads 0..63 own one token ----------
    float zs = 0.f;
    if (tid < MT) {
        float m1 = -1e30f, m2 = -1e30f, m3 = -1e30f;
        int i1 = 0, i2 = 0;
#pragma unroll
        for (int j = 0; j < E_NUM; j++) {
            float v = ls[tid * 65 + j];
            zs += v * v;
            if (v > m1)      { m3 = m2; m2 = m1; i2 = i1; m1 = v; i1 = j; }
            else if (v > m2) { m3 = m2; m2 = v; i2 = j; }
            else if (v > m3) { m3 = v; }
        }
        float s = 0.f;
#pragma unroll
        for (int j = 0; j < E_NUM; j++)
            s += expf(ls[tid * 65 + j] - m1);

        int tok = m0 + tid;
        out[tok * 2 + 0] = (float)i1;
        out[tok * 2 + 1] = (float)i2;
        out[2 * M_TOT + tok * 2 + 0] = 1.0f / s;
        out[2 * M_TOT + tok * 2 + 1] = expf(m2 - m1) / s;
        if ((m1 - m2 < GAP_TH) || (m2 - m3 < GAP_TH)) {
            int p = atomicAdd(&fcnt, 1);
            if (p < 16) flist[p] = tid;
        }
    }

    // ---------- z partial ----------
    if (wid < 2) {
#pragma unroll
        for (int o = 16; o > 0; o >>= 1)
            zs += __shfl_xor_sync(0xffffffffu, zs, o);
        if (lid == 0) zsh[wid] = zs;
    }
    __syncthreads();
    if (tid == 0)
        g_partials[blockIdx.x] = zsh[0] + zsh[1];

    // ---------- inline exact fp32 fixup for ambiguous tokens (rare) ----------
    int nfix = fcnt < 16 ? fcnt : 16;
    for (int i = 0; i < nfix; i++) {
        int tok = m0 + flist[i];
        const float4* xr = (const float4*)(x + (size_t)tok * H_DIM);
#pragma unroll 1
        for (int e8 = 0; e8 < 8; e8++) {
            int e = wid * 8 + e8;
            const float4* wr = (const float4*)(w + (size_t)e * H_DIM);
            float s = 0.f;
#pragma unroll 4
            for (int j = lid; j < H_DIM / 4; j += 32) {
                float4 a = xr[j], b = wr[j];
                s += a.x * b.x + a.y * b.y + a.z * b.z + a.w * b.w;
            }
#pragma unroll
            for (int o = 16; o > 0; o >>= 1)
                s += __shfl_xor_sync(0xffffffffu, s, o);
            if (lid == 0) lg[e] = s;
        }
        __syncthreads();
        if (tid == 0) {
            float m1 = -1e30f, m2 = -1e30f;
            int i1 = 0, i2 = 0;
            for (int j = 0; j < E_NUM; j++) {
                float v = lg[j];
                if (v > m1)      { m2 = m1; i2 = i1; m1 = v; i1 = j; }
                else if (v > m2) { m2 = v; i2 = j; }
            }
            float s2 = 0.f;
            for (int j = 0; j < E_NUM; j++) s2 += expf(lg[j] - m1);
            out[tok * 2 + 0] = (float)i1;
            out[tok * 2 + 1] = (float)i2;
            out[2 * M_TOT + tok * 2 + 0] = 1.0f / s2;
            out[2 * M_TOT + tok * 2 + 1] = expf(m2 - m1) / s2;
        }
        __syncthreads();
    }

    // ---------- last-block finalize (replaces router_finalize kernel) ----------
    if (tid == 0) {
        __threadfence();
        unsigned p = atomicAdd(&g_done, 1);
        is_last = (p == NBLK - 1) ? 1 : 0;
    }
    __syncthreads();
    if (is_last) {
        __threadfence();   // acquire all blocks' g_partials
        ls[tid] = g_partials[tid];       // NTHR == NBLK == 256
        __syncthreads();
#pragma unroll
        for (int s = 128; s > 0; s >>= 1) {
            if (tid < s) ls[tid] += ls[tid + s];
            __syncthreads();
        }
        if (tid == 0) {
            out[4 * M_TOT + 0] = 0.0f;
            out[4 * M_TOT + 1] = ls[0] / ((float)M_TOT * (float)E_NUM);
            g_done = 0;                  // reset for next graph replay
        }
    }
}

extern "C" void kernel_launch(void* const* d_in, const int* in_sizes, int n_in,
                              void* d_out, int out_size)
{
    const float* x = (const float*)d_in[0];   // [4,4096,4096]
    const float* w = (const float*)d_in[1];   // [64,4096]
    float* out = (float*)d_out;

    cudaFuncSetAttribute(router_main, cudaFuncAttributeMaxDynamicSharedMemorySize, DSMB);
    router_main<<<NBLK, NTHR, DSMB>>>(x, w, out);
}

// round 15
// speedup vs baseline: 2.0195x; 2.0195x over previous
#include <cuda_runtime.h>
#include <cuda_bf16.h>
#include <math.h>
#include <stdint.h>

// TopKRouter: x[4,4096,4096] fp32, gate_w[64,4096] fp32
// logits = x @ w^T [16384,64]; softmax; top-2; z_loss = mean(logits^2)
// out fp32: [0,32768) idx | [32768,65536) scores | [65536] aux=0 | [65537] z_loss
//
// sm_103 BASE target. mma.sync bf16 hi/lo split (3 passes), fp32 accumulate.
// A: direct LDG of fragment-pattern float2s -> register cvt (NO smem).
// B: smem staged, double-buffered ldmatrix path.
// MT=64/CTA, 256 thr, grid=256, 2 CTAs/SM. Finalize merged via last-block atomic.
// (R12 hot loop byte-identical; R13's fp16-acc variant spilled at the 128-reg cap.)

#define M_TOT 16384
#define H_DIM 4096
#define E_NUM 64
#define MT    64
#define KC    64
#define NC    (H_DIM / KC)     // 64
#define NBLK  (M_TOT / MT)     // 256
#define NTHR  256
#define GAP_TH 3e-4f

// B stage: BH 0 | BL 8192 ; stage size 16 KB; two stages
#define BH_O 0
#define BL_O 8192
#define BSTG 16384
#define DSMB (1024 + 2 * BSTG)   // 33792

__device__ float g_partials[NBLK];
__device__ unsigned int g_done = 0;

__device__ __forceinline__ uint32_t smem_u32(const void* p) {
    uint32_t a;
    asm("{ .reg .u64 t; cvta.to.shared.u64 t, %1; cvt.u32.u64 %0, t; }" : "=r"(a) : "l"(p));
    return a;
}

#define LDM4(r, a) \
    asm volatile("ldmatrix.sync.aligned.m8n8.x4.shared.b16 {%0,%1,%2,%3}, [%4];" \
        : "=r"((r)[0]), "=r"((r)[1]), "=r"((r)[2]), "=r"((r)[3]) : "r"(a))

#define MMA(c, a, b0, b1) \
    asm volatile("mma.sync.aligned.m16n8k16.row.col.f32.bf16.bf16.f32 " \
        "{%0,%1,%2,%3},{%4,%5,%6,%7},{%8,%9},{%0,%1,%2,%3};" \
        : "+f"((c)[0]), "+f"((c)[1]), "+f"((c)[2]), "+f"((c)[3]) \
        : "r"((a)[0]), "r"((a)[1]), "r"((a)[2]), "r"((a)[3]), "r"(b0), "r"(b1))

// split float4 into bf16 hi/lo quads, store 8B each (swizzled, 128B rows) — B path
__device__ __forceinline__ void cvtst(float4 v, uint32_t hi, uint32_t lo, int row, int q) {
    uint32_t off = (uint32_t)row * 128u + (((uint32_t)q * 8u) ^ (((uint32_t)row & 7u) << 4));
    uint32_t h01, h23, l01, l23;
    asm("cvt.rn.bf16x2.f32 %0, %1, %2;" : "=r"(h01) : "f"(v.y), "f"(v.x));
    asm("cvt.rn.bf16x2.f32 %0, %1, %2;" : "=r"(h23) : "f"(v.w), "f"(v.z));
    float hx = __uint_as_float(h01 << 16), hy = __uint_as_float(h01 & 0xffff0000u);
    float hz = __uint_as_float(h23 << 16), hw = __uint_as_float(h23 & 0xffff0000u);
    asm("cvt.rn.bf16x2.f32 %0, %1, %2;" : "=r"(l01) : "f"(v.y - hy), "f"(v.x - hx));
    asm("cvt.rn.bf16x2.f32 %0, %1, %2;" : "=r"(l23) : "f"(v.w - hw), "f"(v.z - hz));
    asm volatile("st.shared.v2.u32 [%0], {%1,%2};" :: "r"(hi + off), "r"(h01), "r"(h23) : "memory");
    asm volatile("st.shared.v2.u32 [%0], {%1,%2};" :: "r"(lo + off), "r"(l01), "r"(l23) : "memory");
}

// convert one float2 (k-adjacent pair) to bf16x2 hi + lo (elem0 in low half)
__device__ __forceinline__ void cvt2(float2 v, uint32_t& h, uint32_t& l) {
    asm("cvt.rn.bf16x2.f32 %0, %1, %2;" : "=r"(h) : "f"(v.y), "f"(v.x));
    float hx = __uint_as_float(h << 16), hy = __uint_as_float(h & 0xffff0000u);
    asm("cvt.rn.bf16x2.f32 %0, %1, %2;" : "=r"(l) : "f"(v.y - hy), "f"(v.x - hx));
}

extern __shared__ char dsm_raw[];

__global__ __launch_bounds__(NTHR, 2)
void router_main(const float* __restrict__ x, const float* __restrict__ w,
                 float* __restrict__ out)
{
    __shared__ float zsh[2];
    __shared__ float lg[E_NUM];
    __shared__ int flist[16];
    __shared__ int fcnt;
    __shared__ int is_last;

    const int tid  = threadIdx.x;
    const int lid  = tid & 31;
    const int wid  = tid >> 5;               // 0..7
    const int wm   = wid & 1;                // row half (32 tokens)
    const int wn   = (wid >> 1) & 1;         // expert half (32 experts)
    const int kgrp = wid >> 2;               // k half of each chunk (k32)
    const int m0   = blockIdx.x * MT;
    const int kw   = kgrp * 32;

    uint32_t raw = smem_u32(dsm_raw);
    uint32_t SB  = (raw + 127u) & ~127u;

    // B ldmatrix constants
    const uint32_t sxor  = ((uint32_t)(lid & 7)) << 4;
    const uint32_t boff0 = (uint32_t)(wn * 32 + ((lid >> 4) << 3) + (lid & 7)) * 128u;
    const uint32_t boff1 = boff0 + 2048u;    // +16 experts
    const uint32_t bkx   = ((uint32_t)((lid >> 3) & 1)) << 4;

    // A fragment base: row = m0 + wm*32 + (lid>>2), col base = 2*(lid&3)
    const float* aptr = x + (size_t)(m0 + wm * 32 + (lid >> 2)) * H_DIM + 2 * (lid & 3);

    // B staging lanes
    const int brow = tid >> 4, bq = tid & 15;

    float acc[2][4][4];
#pragma unroll
    for (int mi = 0; mi < 2; mi++)
#pragma unroll
        for (int ni = 0; ni < 4; ni++)
#pragma unroll
            for (int r = 0; r < 4; r++) acc[mi][ni][r] = 0.f;

    if (tid == 0) fcnt = 0;

    float2 S0[8], S1[8];
    float4 rb[4];

    // ---------- prologue ----------
#pragma unroll
    for (int slot = 0; slot < 4; slot++)
        rb[slot] = *(const float4*)&w[(size_t)(brow + slot * 16) * H_DIM + bq * 4];
    {
        uint32_t st0 = SB;
#pragma unroll
        for (int slot = 0; slot < 4; slot++)
            cvtst(rb[slot], st0 + BH_O, st0 + BL_O, brow + slot * 16, bq);
    }
#pragma unroll
    for (int mi = 0; mi < 2; mi++) {
        S0[mi * 4 + 0] = *(const float2*)(aptr + (mi * 16 + 0) * H_DIM + kw + 0);
        S0[mi * 4 + 1] = *(const float2*)(aptr + (mi * 16 + 8) * H_DIM + kw + 0);
        S0[mi * 4 + 2] = *(const float2*)(aptr + (mi * 16 + 0) * H_DIM + kw + 8);
        S0[mi * 4 + 3] = *(const float2*)(aptr + (mi * 16 + 8) * H_DIM + kw + 8);
        S1[mi * 4 + 0] = *(const float2*)(aptr + (mi * 16 + 0) * H_DIM + kw + 16);
        S1[mi * 4 + 1] = *(const float2*)(aptr + (mi * 16 + 8) * H_DIM + kw + 16);
        S1[mi * 4 + 2] = *(const float2*)(aptr + (mi * 16 + 0) * H_DIM + kw + 24);
        S1[mi * 4 + 3] = *(const float2*)(aptr + (mi * 16 + 8) * H_DIM + kw + 24);
    }
#pragma unroll
    for (int slot = 0; slot < 4; slot++)
        rb[slot] = *(const float4*)&w[(size_t)(brow + slot * 16) * H_DIM + KC + bq * 4];
    __syncthreads();

    // ---------- main loop ----------
#pragma unroll 1
    for (int c = 0; c < NC; c++) {
        const uint32_t rbuf = SB + ((c & 1) ? BSTG : 0);
        const uint32_t wbuf = SB + ((c & 1) ? 0 : BSTG);
        const uint32_t BH = rbuf + BH_O, BL = rbuf + BL_O;
        const int kc = c * KC + kw;
        const int kA = (c < NC - 1) ? (kc + KC) : kc;
        const int kB = (c < NC - 2) ? ((c + 2) * KC) : ((NC - 1) * KC);

#pragma unroll
        for (int ks = 0; ks < 2; ks++) {
            float2* S = ks ? S1 : S0;
            uint32_t ah[2][4], al[2][4];
#pragma unroll
            for (int mi = 0; mi < 2; mi++)
#pragma unroll
                for (int j = 0; j < 4; j++)
                    cvt2(S[mi * 4 + j], ah[mi][j], al[mi][j]);
            {
                const int kk = kA + ks * 16;
#pragma unroll
                for (int mi = 0; mi < 2; mi++) {
                    S[mi * 4 + 0] = *(const float2*)(aptr + (mi * 16 + 0) * H_DIM + kk + 0);
                    S[mi * 4 + 1] = *(const float2*)(aptr + (mi * 16 + 8) * H_DIM + kk + 0);
                    S[mi * 4 + 2] = *(const float2*)(aptr + (mi * 16 + 0) * H_DIM + kk + 8);
                    S[mi * 4 + 3] = *(const float2*)(aptr + (mi * 16 + 8) * H_DIM + kk + 8);
                }
            }
            const uint32_t kb  = (uint32_t)(kgrp * 2 + ks) * 32u;
            const uint32_t kbb = (kb + bkx) ^ sxor;
#pragma unroll
            for (int nh = 0; nh < 2; nh++) {
                const uint32_t bo = (nh == 0) ? boff0 : boff1;
                uint32_t bHn[4], bLn[4];
                LDM4(bHn, BH + bo + kbb);
                LDM4(bLn, BL + bo + kbb);
#pragma unroll
                for (int mi = 0; mi < 2; mi++)
#pragma unroll
                    for (int nl = 0; nl < 2; nl++)
                        MMA(acc[mi][nh * 2 + nl], ah[mi], bHn[nl * 2], bHn[nl * 2 + 1]);
#pragma unroll
                for (int mi = 0; mi < 2; mi++)
#pragma unroll
                    for (int nl = 0; nl < 2; nl++)
                        MMA(acc[mi][nh * 2 + nl], ah[mi], bLn[nl * 2], bLn[nl * 2 + 1]);
#pragma unroll
                for (int mi = 0; mi < 2; mi++)
#pragma unroll
                    for (int nl = 0; nl < 2; nl++)
                        MMA(acc[mi][nh * 2 + nl], al[mi], bHn[nl * 2], bHn[nl * 2 + 1]);
            }
        }

#pragma unroll
        for (int slot = 0; slot < 4; slot++)
            cvtst(rb[slot], wbuf + BH_O, wbuf + BL_O, brow + slot * 16, bq);
#pragma unroll
        for (int slot = 0; slot < 4; slot++)
            rb[slot] = *(const float4*)&w[(size_t)(brow + slot * 16) * H_DIM + kB + bq * 4];
        __syncthreads();
    }

    // ---------- merge kgrp halves + stage logits [64][65] (overlays B stages) ----------
    float* ls = (float*)(dsm_raw + (SB - raw));
    {
        int gr = lid >> 2, tg = lid & 3;
        if (kgrp == 0) {
#pragma unroll
            for (int mi = 0; mi < 2; mi++)
#pragma unroll
                for (int ni = 0; ni < 4; ni++) {
                    int r0 = wm * 32 + mi * 16 + gr;
                    int col = wn * 32 + ni * 8 + tg * 2;
                    ls[r0 * 65 + col]           = acc[mi][ni][0];
                    ls[r0 * 65 + col + 1]       = acc[mi][ni][1];
                    ls[(r0 + 8) * 65 + col]     = acc[mi][ni][2];
                    ls[(r0 + 8) * 65 + col + 1] = acc[mi][ni][3];
                }
        }
        __syncthreads();
        if (kgrp == 1) {
#pragma unroll
            for (int mi = 0; mi < 2; mi++)
#pragma unroll
                for (int ni = 0; ni < 4; ni++) {
                    int r0 = wm * 32 + mi * 16 + gr;
                    int col = wn * 32 + ni * 8 + tg * 2;
                    ls[r0 * 65 + col]           += acc[mi][ni][0];
                    ls[r0 * 65 + col + 1]       += acc[mi][ni][1];
                    ls[(r0 + 8) * 65 + col]     += acc[mi][ni][2];
                    ls[(r0 + 8) * 65 + col + 1] += acc[mi][ni][3];
                }
        }
        __syncthreads();
    }

    // ---------- per-token epilogue: threads 0..63 own one token ----------
    float zs = 0.f;
    if (tid < MT) {
        float m1 = -1e30f, m2 = -1e30f, m3 = -1e30f;
        int i1 = 0, i2 = 0;
#pragma unroll
        for (int j = 0; j < E_NUM; j++) {
            float v = ls[tid * 65 + j];
            zs += v * v;
            if (v > m1)      { m3 = m2; m2 = m1; i2 = i1; m1 = v; i1 = j; }
            else if (v > m2) { m3 = m2; m2 = v; i2 = j; }
            else if (v > m3) { m3 = v; }
        }
        float s = 0.f;
#pragma unroll
        for (int j = 0; j < E_NUM; j++)
            s += expf(ls[tid * 65 + j] - m1);

        int tok = m0 + tid;
        out[tok * 2 + 0] = (float)i1;
        out[tok * 2 + 1] = (float)i2;
        out[2 * M_TOT + tok * 2 + 0] = 1.0f / s;
        out[2 * M_TOT + tok * 2 + 1] = expf(m2 - m1) / s;
        if ((m1 - m2 < GAP_TH) || (m2 - m3 < GAP_TH)) {
            int p = atomicAdd(&fcnt, 1);
            if (p < 16) flist[p] = tid;
        }
    }

    // ---------- z partial ----------
    if (wid < 2) {
#pragma unroll
        for (int o = 16; o > 0; o >>= 1)
            zs += __shfl_xor_sync(0xffffffffu, zs, o);
        if (lid == 0) zsh[wid] = zs;
    }
    __syncthreads();
    if (tid == 0)
        g_partials[blockIdx.x] = zsh[0] + zsh[1];

    // ---------- inline exact fp32 fixup for ambiguous tokens (rare) ----------
    int nfix = fcnt < 16 ? fcnt : 16;
    for (int i = 0; i < nfix; i++) {
        int tok = m0 + flist[i];
        const float4* xr = (const float4*)(x + (size_t)tok * H_DIM);
#pragma unroll 1
        for (int e8 = 0; e8 < 8; e8++) {
            int e = wid * 8 + e8;
            const float4* wr = (const float4*)(w + (size_t)e * H_DIM);
            float s = 0.f;
#pragma unroll 4
            for (int j = lid; j < H_DIM / 4; j += 32) {
                float4 a = xr[j], b = wr[j];
                s += a.x * b.x + a.y * b.y + a.z * b.z + a.w * b.w;
            }
#pragma unroll
            for (int o = 16; o > 0; o >>= 1)
                s += __shfl_xor_sync(0xffffffffu, s, o);
            if (lid == 0) lg[e] = s;
        }
        __syncthreads();
        if (tid == 0) {
            float m1 = -1e30f, m2 = -1e30f;
            int i1 = 0, i2 = 0;
            for (int j = 0; j < E_NUM; j++) {
                float v = lg[j];
                if (v > m1)      { m2 = m1; i2 = i1; m1 = v; i1 = j; }
                else if (v > m2) { m2 = v; i2 = j; }
            }
            float s2 = 0.f;
            for (int j = 0; j < E_NUM; j++) s2 += expf(lg[j] - m1);
            out[tok * 2 + 0] = (float)i1;
            out[tok * 2 + 1] = (float)i2;
            out[2 * M_TOT + tok * 2 + 0] = 1.0f / s2;
            out[2 * M_TOT + tok * 2 + 1] = expf(m2 - m1) / s2;
        }
        __syncthreads();
    }

    // ---------- last-block finalize (replaces router_finalize kernel) ----------
    if (tid == 0) {
        __threadfence();
        unsigned p = atomicAdd(&g_done, 1);
        is_last = (p == NBLK - 1) ? 1 : 0;
    }
    __syncthreads();
    if (is_last) {
        __threadfence();   // acquire all blocks' g_partials
        ls[tid] = g_partials[tid];       // NTHR == NBLK == 256
        __syncthreads();
#pragma unroll
        for (int s = 128; s > 0; s >>= 1) {
            if (tid < s) ls[tid] += ls[tid + s];
            __syncthreads();
        }
        if (tid == 0) {
            out[4 * M_TOT + 0] = 0.0f;
            out[4 * M_TOT + 1] = ls[0] / ((float)M_TOT * (float)E_NUM);
            g_done = 0;                  // reset for next graph replay
        }
    }
}

extern "C" void kernel_launch(void* const* d_in, const int* in_sizes, int n_in,
                              void* d_out, int out_size)
{
    const float* x = (const float*)d_in[0];   // [4,4096,4096]
    const float* w = (const float*)d_in[1];   // [64,4096]
    float* out = (float*)d_out;

    cudaFuncSetAttribute(router_main, cudaFuncAttributeMaxDynamicSharedMemorySize, DSMB);
    router_main<<<NBLK, NTHR, DSMB>>>(x, w, out);
}

// round 16
// speedup vs baseline: 2.0270x; 1.0037x over previous
#include <cuda_runtime.h>
#include <cuda_bf16.h>
#include <math.h>
#include <stdint.h>

// TopKRouter: x[4,4096,4096] fp32, gate_w[64,4096] fp32
// logits = x @ w^T [16384,64]; softmax; top-2; z_loss = mean(logits^2)
// out fp32: [0,32768) idx | [32768,65536) scores | [65536] aux=0 | [65537] z_loss
//
// sm_103 BASE target. mma.sync bf16 hi/lo split (3 passes), fp32 accumulate.
// A: direct LDG fragment loads, SINGLE prefetch bank at ks-phase distance
//    (frees 16 regs -> no spill under the (256,2) 128-reg cap; R15 spilled).
// B: smem staged, double-buffered ldmatrix path.
// MT=64/CTA, 256 thr, grid=256, 2 CTAs/SM. Finalize merged via last-block atomic.

#define M_TOT 16384
#define H_DIM 4096
#define E_NUM 64
#define MT    64
#define KC    64
#define NC    (H_DIM / KC)     // 64
#define NBLK  (M_TOT / MT)     // 256
#define NTHR  256
#define GAP_TH 3e-4f

// B stage: BH 0 | BL 8192 ; stage size 16 KB; two stages
#define BH_O 0
#define BL_O 8192
#define BSTG 16384
#define DSMB (1024 + 2 * BSTG)   // 33792

__device__ float g_partials[NBLK];
__device__ unsigned int g_done = 0;

__device__ __forceinline__ uint32_t smem_u32(const void* p) {
    uint32_t a;
    asm("{ .reg .u64 t; cvta.to.shared.u64 t, %1; cvt.u32.u64 %0, t; }" : "=r"(a) : "l"(p));
    return a;
}

#define LDM4(r, a) \
    asm volatile("ldmatrix.sync.aligned.m8n8.x4.shared.b16 {%0,%1,%2,%3}, [%4];" \
        : "=r"((r)[0]), "=r"((r)[1]), "=r"((r)[2]), "=r"((r)[3]) : "r"(a))

#define MMA(c, a, b0, b1) \
    asm volatile("mma.sync.aligned.m16n8k16.row.col.f32.bf16.bf16.f32 " \
        "{%0,%1,%2,%3},{%4,%5,%6,%7},{%8,%9},{%0,%1,%2,%3};" \
        : "+f"((c)[0]), "+f"((c)[1]), "+f"((c)[2]), "+f"((c)[3]) \
        : "r"((a)[0]), "r"((a)[1]), "r"((a)[2]), "r"((a)[3]), "r"(b0), "r"(b1))

// split float4 into bf16 hi/lo quads, store 8B each (swizzled, 128B rows) — B path
__device__ __forceinline__ void cvtst(float4 v, uint32_t hi, uint32_t lo, int row, int q) {
    uint32_t off = (uint32_t)row * 128u + (((uint32_t)q * 8u) ^ (((uint32_t)row & 7u) << 4));
    uint32_t h01, h23, l01, l23;
    asm("cvt.rn.bf16x2.f32 %0, %1, %2;" : "=r"(h01) : "f"(v.y), "f"(v.x));
    asm("cvt.rn.bf16x2.f32 %0, %1, %2;" : "=r"(h23) : "f"(v.w), "f"(v.z));
    float hx = __uint_as_float(h01 << 16), hy = __uint_as_float(h01 & 0xffff0000u);
    float hz = __uint_as_float(h23 << 16), hw = __uint_as_float(h23 & 0xffff0000u);
    asm("cvt.rn.bf16x2.f32 %0, %1, %2;" : "=r"(l01) : "f"(v.y - hy), "f"(v.x - hx));
    asm("cvt.rn.bf16x2.f32 %0, %1, %2;" : "=r"(l23) : "f"(v.w - hw), "f"(v.z - hz));
    asm volatile("st.shared.v2.u32 [%0], {%1,%2};" :: "r"(hi + off), "r"(h01), "r"(h23) : "memory");
    asm volatile("st.shared.v2.u32 [%0], {%1,%2};" :: "r"(lo + off), "r"(l01), "r"(l23) : "memory");
}

// convert one float2 (k-adjacent pair) to bf16x2 hi + lo (elem0 in low half)
__device__ __forceinline__ void cvt2(float2 v, uint32_t& h, uint32_t& l) {
    asm("cvt.rn.bf16x2.f32 %0, %1, %2;" : "=r"(h) : "f"(v.y), "f"(v.x));
    float hx = __uint_as_float(h << 16), hy = __uint_as_float(h & 0xffff0000u);
    asm("cvt.rn.bf16x2.f32 %0, %1, %2;" : "=r"(l) : "f"(v.y - hy), "f"(v.x - hx));
}

extern __shared__ char dsm_raw[];

__global__ __launch_bounds__(NTHR, 2)
void router_main(const float* __restrict__ x, const float* __restrict__ w,
                 float* __restrict__ out)
{
    __shared__ float zsh[2];
    __shared__ float lg[E_NUM];
    __shared__ int flist[16];
    __shared__ int fcnt;
    __shared__ int is_last;

    const int tid  = threadIdx.x;
    const int lid  = tid & 31;
    const int wid  = tid >> 5;               // 0..7
    const int wm   = wid & 1;                // row half (32 tokens)
    const int wn   = (wid >> 1) & 1;         // expert half (32 experts)
    const int kgrp = wid >> 2;               // k half of each chunk (k32)
    const int m0   = blockIdx.x * MT;
    const int kw   = kgrp * 32;

    uint32_t raw = smem_u32(dsm_raw);
    uint32_t SB  = (raw + 127u) & ~127u;

    // B ldmatrix constants
    const uint32_t sxor  = ((uint32_t)(lid & 7)) << 4;
    const uint32_t boff0 = (uint32_t)(wn * 32 + ((lid >> 4) << 3) + (lid & 7)) * 128u;
    const uint32_t boff1 = boff0 + 2048u;    // +16 experts
    const uint32_t bkx   = ((uint32_t)((lid >> 3) & 1)) << 4;

    // A fragment base: row = m0 + wm*32 + (lid>>2), col base = 2*(lid&3)
    const float* aptr = x + (size_t)(m0 + wm * 32 + (lid >> 2)) * H_DIM + 2 * (lid & 3);

    // B staging lanes
    const int brow = tid >> 4, bq = tid & 15;

    float acc[2][4][4];
#pragma unroll
    for (int mi = 0; mi < 2; mi++)
#pragma unroll
        for (int ni = 0; ni < 4; ni++)
#pragma unroll
            for (int r = 0; r < 4; r++) acc[mi][ni][r] = 0.f;

    if (tid == 0) fcnt = 0;

    float2 S[8];       // single A slice bank (16 regs; ks-phase prefetch distance)
    float4 rb[4];

    // ---------- prologue ----------
#pragma unroll
    for (int slot = 0; slot < 4; slot++)
        rb[slot] = *(const float4*)&w[(size_t)(brow + slot * 16) * H_DIM + bq * 4];
    {
        uint32_t st0 = SB;
#pragma unroll
        for (int slot = 0; slot < 4; slot++)
            cvtst(rb[slot], st0 + BH_O, st0 + BL_O, brow + slot * 16, bq);
    }
    // first A slice: phase p=0 -> k = kw + 0..15
#pragma unroll
    for (int mi = 0; mi < 2; mi++) {
        S[mi * 4 + 0] = *(const float2*)(aptr + (mi * 16 + 0) * H_DIM + kw + 0);
        S[mi * 4 + 1] = *(const float2*)(aptr + (mi * 16 + 8) * H_DIM + kw + 0);
        S[mi * 4 + 2] = *(const float2*)(aptr + (mi * 16 + 0) * H_DIM + kw + 8);
        S[mi * 4 + 3] = *(const float2*)(aptr + (mi * 16 + 8) * H_DIM + kw + 8);
    }
#pragma unroll
    for (int slot = 0; slot < 4; slot++)
        rb[slot] = *(const float4*)&w[(size_t)(brow + slot * 16) * H_DIM + KC + bq * 4];
    __syncthreads();

    // ---------- main loop ----------
#pragma unroll 1
    for (int c = 0; c < NC; c++) {
        const uint32_t rbuf = SB + ((c & 1) ? BSTG : 0);
        const uint32_t wbuf = SB + ((c & 1) ? 0 : BSTG);
        const uint32_t BH = rbuf + BH_O, BL = rbuf + BL_O;
        const int kB = (c < NC - 2) ? ((c + 2) * KC) : ((NC - 1) * KC);

#pragma unroll
        for (int ks = 0; ks < 2; ks++) {
            // convert current slice -> fragments (frees S)
            uint32_t ah[2][4], al[2][4];
#pragma unroll
            for (int mi = 0; mi < 2; mi++)
#pragma unroll
                for (int j = 0; j < 4; j++)
                    cvt2(S[mi * 4 + j], ah[mi][j], al[mi][j]);
            // prefetch NEXT phase's slice (distance = 1 ks phase ~2000 cyc > DRAM lat)
            {
                int p1 = c * 2 + ks + 1;
                if (p1 > 2 * NC - 1) p1 = 2 * NC - 1;          // clamp (harmless reload)
                const int kk = (p1 >> 1) * KC + kw + (p1 & 1) * 16;
#pragma unroll
                for (int mi = 0; mi < 2; mi++) {
                    S[mi * 4 + 0] = *(const float2*)(aptr + (mi * 16 + 0) * H_DIM + kk + 0);
                    S[mi * 4 + 1] = *(const float2*)(aptr + (mi * 16 + 8) * H_DIM + kk + 0);
                    S[mi * 4 + 2] = *(const float2*)(aptr + (mi * 16 + 0) * H_DIM + kk + 8);
                    S[mi * 4 + 3] = *(const float2*)(aptr + (mi * 16 + 8) * H_DIM + kk + 8);
                }
            }
            // B ldmatrix + MMAs (unchanged)
            const uint32_t kb  = (uint32_t)(kgrp * 2 + ks) * 32u;
            const uint32_t kbb = (kb + bkx) ^ sxor;
#pragma unroll
            for (int nh = 0; nh < 2; nh++) {
                const uint32_t bo = (nh == 0) ? boff0 : boff1;
                uint32_t bHn[4], bLn[4];
                LDM4(bHn, BH + bo + kbb);
                LDM4(bLn, BL + bo + kbb);
#pragma unroll
                for (int mi = 0; mi < 2; mi++)
#pragma unroll
                    for (int nl = 0; nl < 2; nl++)
                        MMA(acc[mi][nh * 2 + nl], ah[mi], bHn[nl * 2], bHn[nl * 2 + 1]);
#pragma unroll
                for (int mi = 0; mi < 2; mi++)
#pragma unroll
                    for (int nl = 0; nl < 2; nl++)
                        MMA(acc[mi][nh * 2 + nl], ah[mi], bLn[nl * 2], bLn[nl * 2 + 1]);
#pragma unroll
                for (int mi = 0; mi < 2; mi++)
#pragma unroll
                    for (int nl = 0; nl < 2; nl++)
                        MMA(acc[mi][nh * 2 + nl], al[mi], bHn[nl * 2], bHn[nl * 2 + 1]);
            }
        }

        // stage B(c+1) from rb, then LDG B(c+2)
#pragma unroll
        for (int slot = 0; slot < 4; slot++)
            cvtst(rb[slot], wbuf + BH_O, wbuf + BL_O, brow + slot * 16, bq);
#pragma unroll
        for (int slot = 0; slot < 4; slot++)
            rb[slot] = *(const float4*)&w[(size_t)(brow + slot * 16) * H_DIM + kB + bq * 4];
        __syncthreads();
    }

    // ---------- merge kgrp halves + stage logits [64][65] (overlays B stages) ----------
    float* ls = (float*)(dsm_raw + (SB - raw));
    {
        int gr = lid >> 2, tg = lid & 3;
        if (kgrp == 0) {
#pragma unroll
            for (int mi = 0; mi < 2; mi++)
#pragma unroll
                for (int ni = 0; ni < 4; ni++) {
                    int r0 = wm * 32 + mi * 16 + gr;
                    int col = wn * 32 + ni * 8 + tg * 2;
                    ls[r0 * 65 + col]           = acc[mi][ni][0];
                    ls[r0 * 65 + col + 1]       = acc[mi][ni][1];
                    ls[(r0 + 8) * 65 + col]     = acc[mi][ni][2];
                    ls[(r0 + 8) * 65 + col + 1] = acc[mi][ni][3];
                }
        }
        __syncthreads();
        if (kgrp == 1) {
#pragma unroll
            for (int mi = 0; mi < 2; mi++)
#pragma unroll
                for (int ni = 0; ni < 4; ni++) {
                    int r0 = wm * 32 + mi * 16 + gr;
                    int col = wn * 32 + ni * 8 + tg * 2;
                    ls[r0 * 65 + col]           += acc[mi][ni][0];
                    ls[r0 * 65 + col + 1]       += acc[mi][ni][1];
                    ls[(r0 + 8) * 65 + col]     += acc[mi][ni][2];
                    ls[(r0 + 8) * 65 + col + 1] += acc[mi][ni][3];
                }
        }
        __syncthreads();
    }

    // ---------- per-token epilogue: threads 0..63 own one token ----------
    float zs = 0.f;
    if (tid < MT) {
        float m1 = -1e30f, m2 = -1e30f, m3 = -1e30f;
        int i1 = 0, i2 = 0;
#pragma unroll
        for (int j = 0; j < E_NUM; j++) {
            float v = ls[tid * 65 + j];
            zs += v * v;
            if (v > m1)      { m3 = m2; m2 = m1; i2 = i1; m1 = v; i1 = j; }
            else if (v > m2) { m3 = m2; m2 = v; i2 = j; }
            else if (v > m3) { m3 = v; }
        }
        float s = 0.f;
#pragma unroll
        for (int j = 0; j < E_NUM; j++)
            s += expf(ls[tid * 65 + j] - m1);

        int tok = m0 + tid;
        out[tok * 2 + 0] = (float)i1;
        out[tok * 2 + 1] = (float)i2;
        out[2 * M_TOT + tok * 2 + 0] = 1.0f / s;
        out[2 * M_TOT + tok * 2 + 1] = expf(m2 - m1) / s;
        if ((m1 - m2 < GAP_TH) || (m2 - m3 < GAP_TH)) {
            int p = atomicAdd(&fcnt, 1);
            if (p < 16) flist[p] = tid;
        }
    }

    // ---------- z partial ----------
    if (wid < 2) {
#pragma unroll
        for (int o = 16; o > 0; o >>= 1)
            zs += __shfl_xor_sync(0xffffffffu, zs, o);
        if (lid == 0) zsh[wid] = zs;
    }
    __syncthreads();
    if (tid == 0)
        g_partials[blockIdx.x] = zsh[0] + zsh[1];

    // ---------- inline exact fp32 fixup for ambiguous tokens (rare) ----------
    int nfix = fcnt < 16 ? fcnt : 16;
    for (int i = 0; i < nfix; i++) {
        int tok = m0 + flist[i];
        const float4* xr = (const float4*)(x + (size_t)tok * H_DIM);
#pragma unroll 1
        for (int e8 = 0; e8 < 8; e8++) {
            int e = wid * 8 + e8;
            const float4* wr = (const float4*)(w + (size_t)e * H_DIM);
            float s = 0.f;
#pragma unroll 4
            for (int j = lid; j < H_DIM / 4; j += 32) {
                float4 a = xr[j], b = wr[j];
                s += a.x * b.x + a.y * b.y + a.z * b.z + a.w * b.w;
            }
#pragma unroll
            for (int o = 16; o > 0; o >>= 1)
                s += __shfl_xor_sync(0xffffffffu, s, o);
            if (lid == 0) lg[e] = s;
        }
        __syncthreads();
        if (tid == 0) {
            float m1 = -1e30f, m2 = -1e30f;
            int i1 = 0, i2 = 0;
            for (int j = 0; j < E_NUM; j++) {
                float v = lg[j];
                if (v > m1)      { m2 = m1; i2 = i1; m1 = v; i1 = j; }
                else if (v > m2) { m2 = v; i2 = j; }
            }
            float s2 = 0.f;
            for (int j = 0; j < E_NUM; j++) s2 += expf(lg[j] - m1);
            out[tok * 2 + 0] = (float)i1;
            out[tok * 2 + 1] = (float)i2;
            out[2 * M_TOT + tok * 2 + 0] = 1.0f / s2;
            out[2 * M_TOT + tok * 2 + 1] = expf(m2 - m1) / s2;
        }
        __syncthreads();
    }

    // ---------- last-block finalize ----------
    if (tid == 0) {
        __threadfence();
        unsigned p = atomicAdd(&g_done, 1);
        is_last = (p == NBLK - 1) ? 1 : 0;
    }
    __syncthreads();
    if (is_last) {
        __threadfence();   // acquire all blocks' g_partials
        ls[tid] = g_partials[tid];       // NTHR == NBLK == 256
        __syncthreads();
#pragma unroll
        for (int s = 128; s > 0; s >>= 1) {
            if (tid < s) ls[tid] += ls[tid + s];
            __syncthreads();
        }
        if (tid == 0) {
            out[4 * M_TOT + 0] = 0.0f;
            out[4 * M_TOT + 1] = ls[0] / ((float)M_TOT * (float)E_NUM);
            g_done = 0;                  // reset for next graph replay
        }
    }
}

extern "C" void kernel_launch(void* const* d_in, const int* in_sizes, int n_in,
                              void* d_out, int out_size)
{
    const float* x = (const float*)d_in[0];   // [4,4096,4096]
    const float* w = (const float*)d_in[1];   // [64,4096]
    float* out = (float*)d_out;

    cudaFuncSetAttribute(router_main, cudaFuncAttributeMaxDynamicSharedMemorySize, DSMB);
    router_main<<<NBLK, NTHR, DSMB>>>(x, w, out);
}